// round 1
// baseline (speedup 1.0000x reference)
#include <cuda_runtime.h>
#include <cuda_bf16.h>
#include <cstdint>

#define N_DIM 2048
#define H_DIM 2048
#define V_DIM 32000

// ---- scratch (static device allocations are the sanctioned workaround) ----
__device__ __nv_bfloat16 g_Wb[(size_t)V_DIM * H_DIM];   // 131 MB
__device__ __nv_bfloat16 g_xb[(size_t)N_DIM * H_DIM];   // 8 MB
__device__ double g_acc;

// ============================================================
// Kernel 1: fp32 -> bf16 conversion for W and x; zero accumulator
// ============================================================
__global__ void convert_kernel(const float* __restrict__ x,
                               const float* __restrict__ W) {
    size_t tid = (size_t)blockIdx.x * blockDim.x + threadIdx.x;
    size_t stride = (size_t)gridDim.x * blockDim.x;
    if (tid == 0) g_acc = 0.0;

    const size_t nW4 = (size_t)V_DIM * H_DIM / 4;
    const float4* W4 = (const float4*)W;
    for (size_t i = tid; i < nW4; i += stride) {
        float4 v = W4[i];
        __nv_bfloat162* dst = (__nv_bfloat162*)(g_Wb + i * 4);
        dst[0] = __floats2bfloat162_rn(v.x, v.y);
        dst[1] = __floats2bfloat162_rn(v.z, v.w);
    }
    const size_t nx4 = (size_t)N_DIM * H_DIM / 4;
    const float4* x4 = (const float4*)x;
    for (size_t i = tid; i < nx4; i += stride) {
        float4 v = x4[i];
        __nv_bfloat162* dst = (__nv_bfloat162*)(g_xb + i * 4);
        dst[0] = __floats2bfloat162_rn(v.x, v.y);
        dst[1] = __floats2bfloat162_rn(v.z, v.w);
    }
}

// ============================================================
// Kernel 2: tiled bf16 GEMM (mma.sync) + fused (logit - y)^2 reduction
//   Block tile: BM=128 (rows of x / N), BN=128 (rows of W / V), BK=64
//   8 warps: 2 (M) x 4 (N), warp tile 64x32
// ============================================================
#define BM 128
#define BN 128
#define BK 64
#define THREADS 256
#define A_STAGE_BYTES (BM * BK * 2)   // 16384
#define B_STAGE_BYTES (BN * BK * 2)   // 16384
#define SMEM_BYTES (2 * (A_STAGE_BYTES + B_STAGE_BYTES))  // 65536

__device__ __forceinline__ uint32_t sw128(uint32_t byte_off) {
    return byte_off ^ ((byte_off >> 3) & 0x70);
}

__device__ __forceinline__ void cp_async16(uint32_t smem_addr, const void* gptr) {
    asm volatile("cp.async.cg.shared.global [%0], [%1], 16;"
                 :: "r"(smem_addr), "l"(gptr));
}

__global__ void __launch_bounds__(THREADS)
gemm_mse_kernel(const float* __restrict__ y) {
    extern __shared__ char smem[];
    // layout: A stage0 | A stage1 | B stage0 | B stage1
    char* As = smem;
    char* Bs = smem + 2 * A_STAGE_BYTES;
    uint32_t sA = (uint32_t)__cvta_generic_to_shared(As);
    uint32_t sB = (uint32_t)__cvta_generic_to_shared(Bs);

    const int tid = threadIdx.x;
    const int lane = tid & 31;
    const int warp = tid >> 5;
    const int warp_m = warp & 1;   // 0..1
    const int warp_n = warp >> 1;  // 0..3

    const int n_blk = blockIdx.x * BM;  // along N (rows of x)
    const int v_blk = blockIdx.y * BN;  // along V (rows of W)

    const __nv_bfloat16* gA = g_xb + (size_t)n_blk * H_DIM;
    const __nv_bfloat16* gB = g_Wb + (size_t)v_blk * H_DIM;

    // ---- loader mapping: 4 chunks of 16B per thread per tile ----
    // chunk id = i*256 + tid ; row = chunk>>3 ; col16 = chunk&7
    const int NK = H_DIM / BK;  // 32

    // prefetch stage 0
    {
        #pragma unroll
        for (int i = 0; i < 4; i++) {
            int chunk = i * THREADS + tid;
            int row = chunk >> 3;
            int c16 = chunk & 7;
            uint32_t soff = sw128((uint32_t)(row * 128 + c16 * 16));
            cp_async16(sA + soff, gA + (size_t)row * H_DIM + c16 * 8);
            cp_async16(sB + soff, gB + (size_t)row * H_DIM + c16 * 8);
        }
        asm volatile("cp.async.commit_group;");
    }

    float c[4][4][4];
    #pragma unroll
    for (int mi = 0; mi < 4; mi++)
        #pragma unroll
        for (int ni = 0; ni < 4; ni++)
            #pragma unroll
            for (int r = 0; r < 4; r++) c[mi][ni][r] = 0.0f;

    // ldmatrix lane addressing precompute
    // A: row = warp_m*64 + mi*16 + (lane & 15); k-chunk offset = (lane>>4)
    const int a_row_base = warp_m * 64 + (lane & 15);
    const int a_kc_lane = lane >> 4;           // 0 or 1
    // B: n = warp_n*32 + pair*16 + (lane&7) + ((lane>>4)<<3); k-chunk = (lane>>3)&1
    const int b_row_base = warp_n * 32 + (lane & 7) + ((lane >> 4) << 3);
    const int b_kc_lane = (lane >> 3) & 1;

    for (int kt = 0; kt < NK; kt++) {
        if (kt + 1 < NK) {
            int st = (kt + 1) & 1;
            const __nv_bfloat16* gAk = gA + (size_t)(kt + 1) * BK;
            const __nv_bfloat16* gBk = gB + (size_t)(kt + 1) * BK;
            #pragma unroll
            for (int i = 0; i < 4; i++) {
                int chunk = i * THREADS + tid;
                int row = chunk >> 3;
                int c16 = chunk & 7;
                uint32_t soff = sw128((uint32_t)(row * 128 + c16 * 16));
                cp_async16(sA + st * A_STAGE_BYTES + soff,
                           gAk + (size_t)row * H_DIM + c16 * 8);
                cp_async16(sB + st * B_STAGE_BYTES + soff,
                           gBk + (size_t)row * H_DIM + c16 * 8);
            }
            asm volatile("cp.async.commit_group;");
            asm volatile("cp.async.wait_group 1;");
        } else {
            asm volatile("cp.async.wait_group 0;");
        }
        __syncthreads();

        const uint32_t aBase = sA + (kt & 1) * A_STAGE_BYTES;
        const uint32_t bBase = sB + (kt & 1) * B_STAGE_BYTES;

        #pragma unroll
        for (int ks = 0; ks < 4; ks++) {
            // load A fragments: 4x ldmatrix.x4
            uint32_t a[4][4];
            #pragma unroll
            for (int mi = 0; mi < 4; mi++) {
                int row = a_row_base + mi * 16;
                int kc = ks * 2 + a_kc_lane;
                uint32_t addr = aBase + (uint32_t)(row * 128) +
                                (uint32_t)((kc ^ (row & 7)) * 16);
                asm volatile(
                    "ldmatrix.sync.aligned.m8n8.x4.shared.b16 {%0,%1,%2,%3}, [%4];"
                    : "=r"(a[mi][0]), "=r"(a[mi][1]), "=r"(a[mi][2]), "=r"(a[mi][3])
                    : "r"(addr));
            }
            // load B fragments: 2x ldmatrix.x4 (each covers n16 x k16)
            uint32_t b[2][4];
            #pragma unroll
            for (int p = 0; p < 2; p++) {
                int row = b_row_base + p * 16;
                int kc = ks * 2 + b_kc_lane;
                uint32_t addr = bBase + (uint32_t)(row * 128) +
                                (uint32_t)((kc ^ (row & 7)) * 16);
                asm volatile(
                    "ldmatrix.sync.aligned.m8n8.x4.shared.b16 {%0,%1,%2,%3}, [%4];"
                    : "=r"(b[p][0]), "=r"(b[p][1]), "=r"(b[p][2]), "=r"(b[p][3])
                    : "r"(addr));
            }
            // mma 4x4
            #pragma unroll
            for (int mi = 0; mi < 4; mi++) {
                #pragma unroll
                for (int ni = 0; ni < 4; ni++) {
                    int p = ni >> 1;
                    int o = (ni & 1) * 2;
                    asm volatile(
                        "mma.sync.aligned.m16n8k16.row.col.f32.bf16.bf16.f32 "
                        "{%0,%1,%2,%3}, {%4,%5,%6,%7}, {%8,%9}, {%0,%1,%2,%3};"
                        : "+f"(c[mi][ni][0]), "+f"(c[mi][ni][1]),
                          "+f"(c[mi][ni][2]), "+f"(c[mi][ni][3])
                        : "r"(a[mi][0]), "r"(a[mi][1]), "r"(a[mi][2]), "r"(a[mi][3]),
                          "r"(b[p][o]), "r"(b[p][o + 1]));
                }
            }
        }
        __syncthreads();
    }

    // ---- epilogue: (logit - y)^2, reduce ----
    const int gr = lane >> 2;        // 0..7
    const int gc = (lane & 3) * 2;   // 0,2,4,6
    float acc = 0.0f;
    #pragma unroll
    for (int mi = 0; mi < 4; mi++) {
        int gn0 = n_blk + warp_m * 64 + mi * 16 + gr;
        #pragma unroll
        for (int ni = 0; ni < 4; ni++) {
            int gv = v_blk + warp_n * 32 + ni * 8 + gc;
            float2 y01 = *(const float2*)(y + (size_t)gn0 * V_DIM + gv);
            float2 y23 = *(const float2*)(y + (size_t)(gn0 + 8) * V_DIM + gv);
            float d0 = c[mi][ni][0] - y01.x;
            float d1 = c[mi][ni][1] - y01.y;
            float d2 = c[mi][ni][2] - y23.x;
            float d3 = c[mi][ni][3] - y23.y;
            acc += d0 * d0 + d1 * d1 + d2 * d2 + d3 * d3;
        }
    }
    // warp reduce
    #pragma unroll
    for (int off = 16; off; off >>= 1)
        acc += __shfl_xor_sync(0xFFFFFFFFu, acc, off);

    __shared__ float red[8];
    if (lane == 0) red[warp] = acc;
    __syncthreads();
    if (warp == 0) {
        float s = (lane < 8) ? red[lane] : 0.0f;
        #pragma unroll
        for (int off = 4; off; off >>= 1)
            s += __shfl_xor_sync(0xFFFFFFFFu, s, off);
        if (lane == 0) atomicAdd(&g_acc, (double)s);
    }
}

// ============================================================
// Kernel 3: finalize
// ============================================================
__global__ void finalize_kernel(float* out) {
    out[0] = (float)(g_acc / ((double)N_DIM * (double)V_DIM));
}

// ============================================================
extern "C" void kernel_launch(void* const* d_in, const int* in_sizes, int n_in,
                              void* d_out, int out_size) {
    (void)in_sizes; (void)n_in; (void)out_size;
    const float* x = (const float*)d_in[0];   // [N, H]
    const float* y = (const float*)d_in[1];   // [N, V]
    const float* W = (const float*)d_in[2];   // [V, H]
    float* out = (float*)d_out;

    static bool attr_set = false;
    if (!attr_set) {
        cudaFuncSetAttribute(gemm_mse_kernel,
                             cudaFuncAttributeMaxDynamicSharedMemorySize,
                             SMEM_BYTES);
        attr_set = true;
    }

    convert_kernel<<<2048, 256>>>(x, W);

    dim3 grid(N_DIM / BM, V_DIM / BN);  // (16, 250): x-fastest -> W stripe L2 reuse
    gemm_mse_kernel<<<grid, THREADS, SMEM_BYTES>>>(y);

    finalize_kernel<<<1, 1>>>(out);
}